// round 1
// baseline (speedup 1.0000x reference)
#include <cuda_runtime.h>
#include <math.h>

// Problem constants
#define T_LEN 16384
#define H_DIM 1024
#define IN_DIM 1024
#define OUT_DIM 1024
#define NCHUNK 128
#define CHUNK_L 128

// Scratch (device globals: allocation-free kernel_launch)
__device__ float g_bu_re[(size_t)T_LEN * H_DIM];
__device__ float g_bu_im[(size_t)T_LEN * H_DIM];
__device__ float g_end_re[NCHUNK * H_DIM];
__device__ float g_end_im[NCHUNK * H_DIM];
__device__ float g_carry_re[NCHUNK * H_DIM];
__device__ float g_carry_im[NCHUNK * H_DIM];
__device__ float g_lam_re[H_DIM];
__device__ float g_lam_im[H_DIM];
__device__ float g_lamL_re[H_DIM];
__device__ float g_lamL_im[H_DIM];
__device__ float g_gam[H_DIM];

// ---------------------------------------------------------------------------
// Prep: lambda = exp(-exp(nu) + i*exp(theta)); gamma = exp(gamma_log);
// lamL = lambda^CHUNK_L
// ---------------------------------------------------------------------------
__global__ void prep_kernel(const float* __restrict__ nu_log,
                            const float* __restrict__ theta_log,
                            const float* __restrict__ gamma_log) {
    int h = blockIdx.x * blockDim.x + threadIdx.x;
    if (h >= H_DIM) return;
    float mod = expf(-expf(nu_log[h]));
    float ph  = expf(theta_log[h]);
    float lr = mod * cosf(ph);
    float li = mod * sinf(ph);
    g_lam_re[h] = lr;
    g_lam_im[h] = li;
    g_gam[h] = expf(gamma_log[h]);
    float pr = 1.f, pi = 0.f;
    #pragma unroll 4
    for (int i = 0; i < CHUNK_L; ++i) {
        float nr = pr * lr - pi * li;
        pi = pr * li + pi * lr;
        pr = nr;
    }
    g_lamL_re[h] = pr;
    g_lamL_im[h] = pi;
}

// ---------------------------------------------------------------------------
// Generic fp32 tiled GEMM: C = alpha * A @ B' + beta * C
//   A: M x K row-major
//   BT=false: B is K x N row-major  (optionally scaled per-k by kscale[k])
//   BT=true : B is N x K row-major (i.e. we compute A @ B^T)
// Tile: 128x128x16, 256 threads, 8x8 per thread.
// ---------------------------------------------------------------------------
#define BM 128
#define BN 128
#define BK 16
#define TM 8
#define TN 8

template <bool BT>
__global__ void __launch_bounds__(256, 2)
gemm_kernel(const float* __restrict__ A, const float* __restrict__ Bmat,
            const float* __restrict__ kscale, float alpha, float beta,
            float* __restrict__ Cout, int M, int N, int K) {
    __shared__ float As[BK][BM];
    __shared__ float Bs[BK][BN];

    const int tid = threadIdx.x;
    const int bm = blockIdx.y * BM;
    const int bn = blockIdx.x * BN;
    const int tx = tid & 15;
    const int ty = tid >> 4;

    // A-load mapping: 128 rows x 16 cols = 512 float4; 2 per thread
    const int lr = tid >> 2;         // 0..63
    const int lc = (tid & 3) << 2;   // 0,4,8,12
    // B-load mapping (row-major K x N): 16 rows x 128 cols
    const int br = tid >> 5;         // 0..7
    const int bc = (tid & 31) << 2;  // 0..124

    float acc[TM][TN];
    #pragma unroll
    for (int i = 0; i < TM; ++i)
        #pragma unroll
        for (int j = 0; j < TN; ++j) acc[i][j] = 0.f;

    for (int k0 = 0; k0 < K; k0 += BK) {
        // Load A tile (transposed into smem)
        #pragma unroll
        for (int r = 0; r < 2; ++r) {
            int m = lr + r * 64;
            const float4 v = *reinterpret_cast<const float4*>(
                &A[(size_t)(bm + m) * K + k0 + lc]);
            As[lc + 0][m] = v.x;
            As[lc + 1][m] = v.y;
            As[lc + 2][m] = v.z;
            As[lc + 3][m] = v.w;
        }
        // Load B tile
        if (BT) {
            #pragma unroll
            for (int r = 0; r < 2; ++r) {
                int n = lr + r * 64;
                const float4 v = *reinterpret_cast<const float4*>(
                    &Bmat[(size_t)(bn + n) * K + k0 + lc]);
                Bs[lc + 0][n] = v.x;
                Bs[lc + 1][n] = v.y;
                Bs[lc + 2][n] = v.z;
                Bs[lc + 3][n] = v.w;
            }
        } else {
            #pragma unroll
            for (int r = 0; r < 2; ++r) {
                int k = br + r * 8;
                float4 v = *reinterpret_cast<const float4*>(
                    &Bmat[(size_t)(k0 + k) * N + bn + bc]);
                if (kscale != nullptr) {
                    float s = kscale[k0 + k];
                    v.x *= s; v.y *= s; v.z *= s; v.w *= s;
                }
                *reinterpret_cast<float4*>(&Bs[k][bc]) = v;
            }
        }
        __syncthreads();

        #pragma unroll
        for (int kk = 0; kk < BK; ++kk) {
            float af[TM], bf[TN];
            *reinterpret_cast<float4*>(&af[0]) =
                *reinterpret_cast<const float4*>(&As[kk][ty * TM]);
            *reinterpret_cast<float4*>(&af[4]) =
                *reinterpret_cast<const float4*>(&As[kk][ty * TM + 4]);
            *reinterpret_cast<float4*>(&bf[0]) =
                *reinterpret_cast<const float4*>(&Bs[kk][tx * TN]);
            *reinterpret_cast<float4*>(&bf[4]) =
                *reinterpret_cast<const float4*>(&Bs[kk][tx * TN + 4]);
            #pragma unroll
            for (int i = 0; i < TM; ++i)
                #pragma unroll
                for (int j = 0; j < TN; ++j)
                    acc[i][j] = fmaf(af[i], bf[j], acc[i][j]);
        }
        __syncthreads();
    }

    // Epilogue
    #pragma unroll
    for (int i = 0; i < TM; ++i) {
        size_t row = (size_t)(bm + ty * TM + i) * N + bn + tx * TN;
        #pragma unroll
        for (int j = 0; j < TN; j += 4) {
            float4 o;
            o.x = alpha * acc[i][j + 0];
            o.y = alpha * acc[i][j + 1];
            o.z = alpha * acc[i][j + 2];
            o.w = alpha * acc[i][j + 3];
            if (beta != 0.f) {
                float4 c = *reinterpret_cast<float4*>(&Cout[row + j]);
                o.x += beta * c.x;
                o.y += beta * c.y;
                o.z += beta * c.z;
                o.w += beta * c.w;
            }
            *reinterpret_cast<float4*>(&Cout[row + j]) = o;
        }
    }
}

// ---------------------------------------------------------------------------
// Scan pass 1: per (h, chunk) local scan with zero init, in place over Bu.
// ---------------------------------------------------------------------------
__global__ void scan_local_kernel() {
    int h = blockIdx.x * blockDim.x + threadIdx.x;
    int c = blockIdx.y;
    float lr = g_lam_re[h], li = g_lam_im[h];
    float sr = 0.f, si = 0.f;
    int base = c * CHUNK_L;
    #pragma unroll 4
    for (int j = 0; j < CHUNK_L; ++j) {
        size_t idx = (size_t)(base + j) * H_DIM + h;
        float ur = g_bu_re[idx];
        float ui = g_bu_im[idx];
        float nr = lr * sr - li * si + ur;
        float ni = lr * si + li * sr + ui;
        sr = nr; si = ni;
        g_bu_re[idx] = sr;
        g_bu_im[idx] = si;
    }
    g_end_re[c * H_DIM + h] = sr;
    g_end_im[c * H_DIM + h] = si;
}

// ---------------------------------------------------------------------------
// Scan pass 2: carry chain across chunks (per h).
// carry[k] = true state entering chunk k.
// ---------------------------------------------------------------------------
__global__ void scan_carry_kernel() {
    int h = blockIdx.x * blockDim.x + threadIdx.x;
    float Lr = g_lamL_re[h], Li = g_lamL_im[h];
    float cr = 0.f, ci = 0.f;
    for (int k = 0; k < NCHUNK; ++k) {
        g_carry_re[k * H_DIM + h] = cr;
        g_carry_im[k * H_DIM + h] = ci;
        float er = g_end_re[k * H_DIM + h];
        float ei = g_end_im[k * H_DIM + h];
        float nr = Lr * cr - Li * ci + er;
        float ni = Lr * ci + Li * cr + ei;
        cr = nr; ci = ni;
    }
}

// ---------------------------------------------------------------------------
// Scan pass 3: fixup — h[t0+j] += lambda^{j+1} * carry[chunk]
// ---------------------------------------------------------------------------
__global__ void scan_fix_kernel() {
    int h = blockIdx.x * blockDim.x + threadIdx.x;
    int c = blockIdx.y + 1;  // chunk 0 has zero carry — skip
    float Sr = g_carry_re[c * H_DIM + h];
    float Si = g_carry_im[c * H_DIM + h];
    float lr = g_lam_re[h], li = g_lam_im[h];
    float pr = lr, pi = li;
    int base = c * CHUNK_L;
    #pragma unroll 4
    for (int j = 0; j < CHUNK_L; ++j) {
        size_t idx = (size_t)(base + j) * H_DIM + h;
        g_bu_re[idx] += pr * Sr - pi * Si;
        g_bu_im[idx] += pr * Si + pi * Sr;
        float nr = pr * lr - pi * li;
        pi = pr * li + pi * lr;
        pr = nr;
    }
}

// ---------------------------------------------------------------------------
// Launch
// ---------------------------------------------------------------------------
extern "C" void kernel_launch(void* const* d_in, const int* in_sizes, int n_in,
                              void* d_out, int out_size) {
    const float* x     = (const float*)d_in[0];  // (T, IN)
    const float* nu    = (const float*)d_in[1];  // (H)
    const float* th    = (const float*)d_in[2];  // (H)
    const float* ga    = (const float*)d_in[3];  // (H)
    const float* B_re  = (const float*)d_in[4];  // (IN, H)
    const float* B_im  = (const float*)d_in[5];  // (IN, H)
    const float* C_re  = (const float*)d_in[6];  // (OUT, H)
    const float* C_im  = (const float*)d_in[7];  // (OUT, H)
    const float* Dm    = (const float*)d_in[8];  // (IN, OUT) per einsum 'io'
    float* out = (float*)d_out;

    float *bu_re, *bu_im, *gam;
    cudaGetSymbolAddress((void**)&bu_re, g_bu_re);
    cudaGetSymbolAddress((void**)&bu_im, g_bu_im);
    cudaGetSymbolAddress((void**)&gam, g_gam);

    prep_kernel<<<H_DIM / 256, 256>>>(nu, th, ga);

    dim3 gemm_grid(OUT_DIM / BN, T_LEN / BM);  // (8, 128)

    // Bu = x @ (gamma ⊙ B)
    gemm_kernel<false><<<gemm_grid, 256>>>(x, B_re, gam, 1.f, 0.f, bu_re,
                                           T_LEN, H_DIM, IN_DIM);
    gemm_kernel<false><<<gemm_grid, 256>>>(x, B_im, gam, 1.f, 0.f, bu_im,
                                           T_LEN, H_DIM, IN_DIM);

    // Diagonal complex scan (chunked)
    scan_local_kernel<<<dim3(H_DIM / 256, NCHUNK), 256>>>();
    scan_carry_kernel<<<H_DIM / 256, 256>>>();
    scan_fix_kernel<<<dim3(H_DIM / 256, NCHUNK - 1), 256>>>();

    // out = h_re @ C_re^T - h_im @ C_im^T + x @ D
    gemm_kernel<true><<<gemm_grid, 256>>>(bu_re, C_re, nullptr, 1.f, 0.f, out,
                                          T_LEN, OUT_DIM, H_DIM);
    gemm_kernel<true><<<gemm_grid, 256>>>(bu_im, C_im, nullptr, -1.f, 1.f, out,
                                          T_LEN, OUT_DIM, H_DIM);
    gemm_kernel<false><<<gemm_grid, 256>>>(x, Dm, nullptr, 1.f, 1.f, out,
                                           T_LEN, OUT_DIM, IN_DIM);
}

// round 4
// speedup vs baseline: 3.2157x; 3.2157x over previous
#include <cuda_runtime.h>
#include <cstdint>
#include <math.h>

// Problem constants
#define T_LEN 16384
#define H_DIM 1024
#define IN_DIM 1024
#define OUT_DIM 1024
#define NCHUNK 128
#define CHUNK_L 128

// ---------------------------------------------------------------------------
// Scratch (device globals: allocation-free kernel_launch)
// ---------------------------------------------------------------------------
__device__ float g_bu_re[(size_t)T_LEN * H_DIM];
__device__ float g_bu_im[(size_t)T_LEN * H_DIM];
__device__ float g_end_re[NCHUNK * H_DIM];
__device__ float g_end_im[NCHUNK * H_DIM];
__device__ float g_carry_re[NCHUNK * H_DIM];
__device__ float g_carry_im[NCHUNK * H_DIM];
__device__ float g_lam_re[H_DIM];
__device__ float g_lam_im[H_DIM];
__device__ float g_lamL_re[H_DIM];
__device__ float g_lamL_im[H_DIM];
__device__ float g_gam[H_DIM];
// Preprocessed weights ([N][K] row-major, i.e. K-contiguous per output col)
__device__ float g_Bt_re[(size_t)H_DIM * IN_DIM];   // Bt[h][i] = B_re[i][h]*gam[i]
__device__ float g_Bt_im[(size_t)H_DIM * IN_DIM];
__device__ float g_Dt[(size_t)OUT_DIM * IN_DIM];    // Dt[o][i] = D[i][o]
__device__ float g_nCim[(size_t)OUT_DIM * H_DIM];   // -C_im

// ---------------------------------------------------------------------------
// Helpers: cp.async + mma.sync (all sm_80+ portable PTX — no 'a'-arch needed)
// ---------------------------------------------------------------------------
__device__ __forceinline__ uint32_t smem_u32(const void* p) {
    uint32_t a;
    asm("{ .reg .u64 t; cvta.to.shared.u64 t, %1; cvt.u32.u64 %0, t; }"
        : "=r"(a) : "l"(p));
    return a;
}
__device__ __forceinline__ void cp_async16(uint32_t sa, const void* g) {
    asm volatile("cp.async.cg.shared.global [%0], [%1], 16;" :: "r"(sa), "l"(g));
}
#define CP_COMMIT() asm volatile("cp.async.commit_group;" ::: "memory")
#define CP_WAIT(n)  asm volatile("cp.async.wait_group %0;" :: "n"(n) : "memory")

#define MMA_TF32(c, a, b0, b1)                                              \
    asm volatile("mma.sync.aligned.m16n8k8.row.col.f32.tf32.tf32.f32 "      \
        "{%0,%1,%2,%3}, {%4,%5,%6,%7}, {%8,%9}, {%0,%1,%2,%3};"             \
        : "+f"((c)[0]), "+f"((c)[1]), "+f"((c)[2]), "+f"((c)[3])            \
        : "r"((a)[0]), "r"((a)[1]), "r"((a)[2]), "r"((a)[3]),               \
          "r"(b0), "r"(b1))

// Tile geometry: block 128x128, BK=32; smem tiles [128][32] padded to stride 36
#define SSTRIDE 36
#define TILE_F (128 * SSTRIDE)        // floats per tile (incl. pad)
#define TILE_B (TILE_F * 4)

// Load a 128x32 fp32 tile (row stride 1024 floats in gmem) into smem tile.
// 256 threads, 4x cp.async(16B) each.
__device__ __forceinline__ void load_tile(float* sdst, const float* __restrict__ g) {
    int t = threadIdx.x;
    #pragma unroll
    for (int j = 0; j < 4; ++j) {
        int c = t + 256 * j;          // 0..1023 16B-chunks
        int row = c >> 3, col = c & 7;
        cp_async16(smem_u32(sdst + row * SSTRIDE + col * 4),
                   g + (size_t)row * 1024 + col * 4);
    }
}

// ---------------------------------------------------------------------------
// Prep: lambda, gamma, lambda^CHUNK_L
// ---------------------------------------------------------------------------
__global__ void prep_kernel(const float* __restrict__ nu_log,
                            const float* __restrict__ theta_log,
                            const float* __restrict__ gamma_log) {
    int h = blockIdx.x * blockDim.x + threadIdx.x;
    if (h >= H_DIM) return;
    float mod = expf(-expf(nu_log[h]));
    float ph = expf(theta_log[h]);
    float lr = mod * cosf(ph);
    float li = mod * sinf(ph);
    g_lam_re[h] = lr;
    g_lam_im[h] = li;
    g_gam[h] = expf(gamma_log[h]);
    float pr = 1.f, pi = 0.f;
    #pragma unroll 4
    for (int i = 0; i < CHUNK_L; ++i) {
        float nr = pr * lr - pi * li;
        pi = pr * li + pi * lr;
        pr = nr;
    }
    g_lamL_re[h] = pr;
    g_lamL_im[h] = pi;
}

// ---------------------------------------------------------------------------
// Transpose 1024x1024: dst[j][i] = src[i][j] * (rowscale ? rowscale[i] : 1)
// ---------------------------------------------------------------------------
__global__ void transpose_kernel(const float* __restrict__ src,
                                 float* __restrict__ dst,
                                 const float* __restrict__ rowscale) {
    __shared__ float t[32][33];
    int bx = blockIdx.x * 32, by = blockIdx.y * 32;
    int x = threadIdx.x, y = threadIdx.y;
    #pragma unroll
    for (int r = 0; r < 32; r += 8) {
        int i = by + y + r;
        float s = rowscale ? rowscale[i] : 1.f;
        t[y + r][x] = src[(size_t)i * 1024 + bx + x] * s;
    }
    __syncthreads();
    #pragma unroll
    for (int r = 0; r < 32; r += 8)
        dst[(size_t)(bx + y + r) * 1024 + by + x] = t[x][y + r];
}

__global__ void negate_kernel(const float* __restrict__ src, float* __restrict__ dst) {
    size_t i = (size_t)(blockIdx.x * blockDim.x + threadIdx.x) * 4;
    float4 v = *reinterpret_cast<const float4*>(src + i);
    v.x = -v.x; v.y = -v.y; v.z = -v.z; v.w = -v.w;
    *reinterpret_cast<float4*>(dst + i) = v;
}

// ---------------------------------------------------------------------------
// Fused Bu GEMM: bu_re = x @ Bt_re^T, bu_im = x @ Bt_im^T  (mma.sync tf32)
// Block 128x128, 8 warps as 2(m) x 4(n); warp tile 64x32; dual accumulators.
// ---------------------------------------------------------------------------
#define BU_SMEM (6 * TILE_B)   // A x2, Bre x2, Bim x2 = 110592 B

__global__ void __launch_bounds__(256, 1)
bu_gemm_kernel(const float* __restrict__ X) {
    extern __shared__ float smem[];
    float* As  = smem;               // 2 buffers
    float* Bre = smem + 2 * TILE_F;
    float* Bim = smem + 4 * TILE_F;

    const int tid = threadIdx.x;
    const int lane = tid & 31, qid = lane >> 2, qtr = lane & 3;
    const int wid = tid >> 5, wm = wid & 1, wn = wid >> 1;
    const int bn = blockIdx.x * 128, bm = blockIdx.y * 128;

    const float* Ag = X + (size_t)bm * 1024;
    const float* Brg = g_Bt_re + (size_t)bn * 1024;
    const float* Big = g_Bt_im + (size_t)bn * 1024;

    float cre[4][4][4], cim[4][4][4];
    #pragma unroll
    for (int i = 0; i < 4; ++i)
        #pragma unroll
        for (int j = 0; j < 4; ++j)
            #pragma unroll
            for (int k = 0; k < 4; ++k) { cre[i][j][k] = 0.f; cim[i][j][k] = 0.f; }

    // prefetch chunk 0
    load_tile(As, Ag); load_tile(Bre, Brg); load_tile(Bim, Big);
    CP_COMMIT();

    #pragma unroll 1
    for (int c = 0; c < 32; ++c) {
        int b = c & 1;
        if (c + 1 < 32) {
            int nb = 1 - b;
            const float* off = (const float*)0;
            load_tile(As + nb * TILE_F, Ag + (c + 1) * 32);
            load_tile(Bre + nb * TILE_F, Brg + (c + 1) * 32);
            load_tile(Bim + nb * TILE_F, Big + (c + 1) * 32);
            CP_COMMIT();
            CP_WAIT(1);
            (void)off;
        } else {
            CP_WAIT(0);
        }
        __syncthreads();

        const float* a_s = As + b * TILE_F + (wm * 64 + qid) * SSTRIDE;
        const float* br_s = Bre + b * TILE_F + (wn * 32 + qid) * SSTRIDE;
        const float* bi_s = Bim + b * TILE_F + (wn * 32 + qid) * SSTRIDE;

        #pragma unroll
        for (int s = 0; s < 4; ++s) {
            int ko = s * 8 + qtr;
            uint32_t a[4][4];
            #pragma unroll
            for (int mt = 0; mt < 4; ++mt) {
                const float* ap = a_s + mt * 16 * SSTRIDE + ko;
                a[mt][0] = __float_as_uint(ap[0]);
                a[mt][1] = __float_as_uint(ap[8 * SSTRIDE]);
                a[mt][2] = __float_as_uint(ap[4]);
                a[mt][3] = __float_as_uint(ap[8 * SSTRIDE + 4]);
            }
            #pragma unroll
            for (int nt = 0; nt < 4; ++nt) {
                const float* bp = br_s + nt * 8 * SSTRIDE + ko;
                uint32_t br0 = __float_as_uint(bp[0]);
                uint32_t br1 = __float_as_uint(bp[4]);
                const float* bq = bi_s + nt * 8 * SSTRIDE + ko;
                uint32_t bi0 = __float_as_uint(bq[0]);
                uint32_t bi1 = __float_as_uint(bq[4]);
                #pragma unroll
                for (int mt = 0; mt < 4; ++mt) {
                    MMA_TF32(cre[mt][nt], a[mt], br0, br1);
                    MMA_TF32(cim[mt][nt], a[mt], bi0, bi1);
                }
            }
        }
        __syncthreads();
    }

    // epilogue
    #pragma unroll
    for (int mt = 0; mt < 4; ++mt) {
        int r = bm + wm * 64 + mt * 16 + qid;
        #pragma unroll
        for (int nt = 0; nt < 4; ++nt) {
            int cc = bn + wn * 32 + nt * 8 + 2 * qtr;
            *reinterpret_cast<float2*>(g_bu_re + (size_t)r * 1024 + cc) =
                make_float2(cre[mt][nt][0], cre[mt][nt][1]);
            *reinterpret_cast<float2*>(g_bu_re + (size_t)(r + 8) * 1024 + cc) =
                make_float2(cre[mt][nt][2], cre[mt][nt][3]);
            *reinterpret_cast<float2*>(g_bu_im + (size_t)r * 1024 + cc) =
                make_float2(cim[mt][nt][0], cim[mt][nt][1]);
            *reinterpret_cast<float2*>(g_bu_im + (size_t)(r + 8) * 1024 + cc) =
                make_float2(cim[mt][nt][2], cim[mt][nt][3]);
        }
    }
}

// ---------------------------------------------------------------------------
// Fused output GEMM: out = bu_re@C_re^T + bu_im@(-C_im)^T + x@Dt^T
// 3 K-segments of 1024 each, accumulated in registers. 96 BK=32 chunks.
// ---------------------------------------------------------------------------
#define OUT_SMEM (4 * TILE_B)   // A x2, B x2 = 73728 B

__global__ void __launch_bounds__(256, 1)
out_gemm_kernel(const float* __restrict__ X, const float* __restrict__ Cre,
                float* __restrict__ out) {
    extern __shared__ float smem[];
    float* As = smem;
    float* Bs = smem + 2 * TILE_F;

    const int tid = threadIdx.x;
    const int lane = tid & 31, qid = lane >> 2, qtr = lane & 3;
    const int wid = tid >> 5, wm = wid & 1, wn = wid >> 1;
    const int bn = blockIdx.x * 128, bm = blockIdx.y * 128;

    const float* Aseg[3];
    const float* Bseg[3];
    Aseg[0] = g_bu_re + (size_t)bm * 1024;
    Aseg[1] = g_bu_im + (size_t)bm * 1024;
    Aseg[2] = X + (size_t)bm * 1024;
    Bseg[0] = Cre + (size_t)bn * 1024;
    Bseg[1] = g_nCim + (size_t)bn * 1024;
    Bseg[2] = g_Dt + (size_t)bn * 1024;

    float acc[4][4][4];
    #pragma unroll
    for (int i = 0; i < 4; ++i)
        #pragma unroll
        for (int j = 0; j < 4; ++j)
            #pragma unroll
            for (int k = 0; k < 4; ++k) acc[i][j][k] = 0.f;

    load_tile(As, Aseg[0]); load_tile(Bs, Bseg[0]);
    CP_COMMIT();

    #pragma unroll 1
    for (int c = 0; c < 96; ++c) {
        int b = c & 1;
        if (c + 1 < 96) {
            int nb = 1 - b;
            int s = (c + 1) >> 5, kk = ((c + 1) & 31) * 32;
            load_tile(As + nb * TILE_F, Aseg[s] + kk);
            load_tile(Bs + nb * TILE_F, Bseg[s] + kk);
            CP_COMMIT();
            CP_WAIT(1);
        } else {
            CP_WAIT(0);
        }
        __syncthreads();

        const float* a_s = As + b * TILE_F + (wm * 64 + qid) * SSTRIDE;
        const float* b_s = Bs + b * TILE_F + (wn * 32 + qid) * SSTRIDE;

        #pragma unroll
        for (int s = 0; s < 4; ++s) {
            int ko = s * 8 + qtr;
            uint32_t a[4][4];
            #pragma unroll
            for (int mt = 0; mt < 4; ++mt) {
                const float* ap = a_s + mt * 16 * SSTRIDE + ko;
                a[mt][0] = __float_as_uint(ap[0]);
                a[mt][1] = __float_as_uint(ap[8 * SSTRIDE]);
                a[mt][2] = __float_as_uint(ap[4]);
                a[mt][3] = __float_as_uint(ap[8 * SSTRIDE + 4]);
            }
            #pragma unroll
            for (int nt = 0; nt < 4; ++nt) {
                const float* bp = b_s + nt * 8 * SSTRIDE + ko;
                uint32_t b0 = __float_as_uint(bp[0]);
                uint32_t b1 = __float_as_uint(bp[4]);
                #pragma unroll
                for (int mt = 0; mt < 4; ++mt)
                    MMA_TF32(acc[mt][nt], a[mt], b0, b1);
            }
        }
        __syncthreads();
    }

    #pragma unroll
    for (int mt = 0; mt < 4; ++mt) {
        int r = bm + wm * 64 + mt * 16 + qid;
        #pragma unroll
        for (int nt = 0; nt < 4; ++nt) {
            int cc = bn + wn * 32 + nt * 8 + 2 * qtr;
            *reinterpret_cast<float2*>(out + (size_t)r * 1024 + cc) =
                make_float2(acc[mt][nt][0], acc[mt][nt][1]);
            *reinterpret_cast<float2*>(out + (size_t)(r + 8) * 1024 + cc) =
                make_float2(acc[mt][nt][2], acc[mt][nt][3]);
        }
    }
}

// ---------------------------------------------------------------------------
// Scan pass 1: per (h, chunk) local scan, in place over Bu.
// ---------------------------------------------------------------------------
__global__ void scan_local_kernel() {
    int h = blockIdx.x * blockDim.x + threadIdx.x;
    int c = blockIdx.y;
    float lr = g_lam_re[h], li = g_lam_im[h];
    float sr = 0.f, si = 0.f;
    int base = c * CHUNK_L;
    #pragma unroll 4
    for (int j = 0; j < CHUNK_L; ++j) {
        size_t idx = (size_t)(base + j) * H_DIM + h;
        float ur = g_bu_re[idx];
        float ui = g_bu_im[idx];
        float nr = lr * sr - li * si + ur;
        float ni = lr * si + li * sr + ui;
        sr = nr; si = ni;
        g_bu_re[idx] = sr;
        g_bu_im[idx] = si;
    }
    g_end_re[c * H_DIM + h] = sr;
    g_end_im[c * H_DIM + h] = si;
}

// ---------------------------------------------------------------------------
// Scan pass 2: carry chain across chunks (per h).
// ---------------------------------------------------------------------------
__global__ void scan_carry_kernel() {
    int h = blockIdx.x * blockDim.x + threadIdx.x;
    float Lr = g_lamL_re[h], Li = g_lamL_im[h];
    float cr = 0.f, ci = 0.f;
    for (int k = 0; k < NCHUNK; ++k) {
        g_carry_re[k * H_DIM + h] = cr;
        g_carry_im[k * H_DIM + h] = ci;
        float er = g_end_re[k * H_DIM + h];
        float ei = g_end_im[k * H_DIM + h];
        float nr = Lr * cr - Li * ci + er;
        float ni = Lr * ci + Li * cr + ei;
        cr = nr; ci = ni;
    }
}

// ---------------------------------------------------------------------------
// Scan pass 3: fixup — h[t0+j] += lambda^{j+1} * carry[chunk]
// ---------------------------------------------------------------------------
__global__ void scan_fix_kernel() {
    int h = blockIdx.x * blockDim.x + threadIdx.x;
    int c = blockIdx.y + 1;
    float Sr = g_carry_re[c * H_DIM + h];
    float Si = g_carry_im[c * H_DIM + h];
    float lr = g_lam_re[h], li = g_lam_im[h];
    float pr = lr, pi = li;
    int base = c * CHUNK_L;
    #pragma unroll 4
    for (int j = 0; j < CHUNK_L; ++j) {
        size_t idx = (size_t)(base + j) * H_DIM + h;
        g_bu_re[idx] += pr * Sr - pi * Si;
        g_bu_im[idx] += pr * Si + pi * Sr;
        float nr = pr * lr - pi * li;
        pi = pr * li + pi * lr;
        pr = nr;
    }
}

// ---------------------------------------------------------------------------
// Launch
// ---------------------------------------------------------------------------
extern "C" void kernel_launch(void* const* d_in, const int* in_sizes, int n_in,
                              void* d_out, int out_size) {
    const float* x    = (const float*)d_in[0];
    const float* nu   = (const float*)d_in[1];
    const float* th   = (const float*)d_in[2];
    const float* ga   = (const float*)d_in[3];
    const float* B_re = (const float*)d_in[4];
    const float* B_im = (const float*)d_in[5];
    const float* C_re = (const float*)d_in[6];
    const float* C_im = (const float*)d_in[7];
    const float* Dm   = (const float*)d_in[8];
    float* out = (float*)d_out;

    float *bt_re, *bt_im, *dt, *ncim, *gam;
    cudaGetSymbolAddress((void**)&bt_re, g_Bt_re);
    cudaGetSymbolAddress((void**)&bt_im, g_Bt_im);
    cudaGetSymbolAddress((void**)&dt, g_Dt);
    cudaGetSymbolAddress((void**)&ncim, g_nCim);
    cudaGetSymbolAddress((void**)&gam, g_gam);

    cudaFuncSetAttribute(bu_gemm_kernel, cudaFuncAttributeMaxDynamicSharedMemorySize, BU_SMEM);
    cudaFuncSetAttribute(out_gemm_kernel, cudaFuncAttributeMaxDynamicSharedMemorySize, OUT_SMEM);

    prep_kernel<<<H_DIM / 256, 256>>>(nu, th, ga);

    dim3 tgrid(32, 32), tblk(32, 8);
    transpose_kernel<<<tgrid, tblk>>>(B_re, bt_re, gam);
    transpose_kernel<<<tgrid, tblk>>>(B_im, bt_im, gam);
    transpose_kernel<<<tgrid, tblk>>>(Dm, dt, nullptr);
    negate_kernel<<<(OUT_DIM * H_DIM / 4) / 256, 256>>>(C_im, ncim);

    dim3 ggrid(H_DIM / 128, T_LEN / 128);  // (8, 128)
    bu_gemm_kernel<<<ggrid, 256, BU_SMEM>>>(x);

    scan_local_kernel<<<dim3(H_DIM / 256, NCHUNK), 256>>>();
    scan_carry_kernel<<<H_DIM / 256, 256>>>();
    scan_fix_kernel<<<dim3(H_DIM / 256, NCHUNK - 1), 256>>>();

    out_gemm_kernel<<<ggrid, 256, OUT_SMEM>>>(x, C_re, out);
}

// round 6
// speedup vs baseline: 3.6767x; 1.1434x over previous
#include <cuda_runtime.h>
#include <cstdint>
#include <math.h>

// Problem constants
#define T_LEN 16384
#define H_DIM 1024
#define IN_DIM 1024
#define OUT_DIM 1024
#define NCHUNK 128
#define CHUNK_L 128

// ---------------------------------------------------------------------------
// Scratch (device globals: allocation-free kernel_launch)
// ---------------------------------------------------------------------------
__device__ float g_bu_re[(size_t)T_LEN * H_DIM];
__device__ float g_bu_im[(size_t)T_LEN * H_DIM];
__device__ float g_end_re[NCHUNK * H_DIM];
__device__ float g_end_im[NCHUNK * H_DIM];
__device__ float g_carry_re[NCHUNK * H_DIM];
__device__ float g_carry_im[NCHUNK * H_DIM];
__device__ float g_lam_re[H_DIM];
__device__ float g_lam_im[H_DIM];
__device__ float g_lamL_re[H_DIM];
__device__ float g_lamL_im[H_DIM];
__device__ float g_gam[H_DIM];
// Preprocessed weights ([N][K] row-major, K-contiguous)
__device__ float g_Bt_re[(size_t)H_DIM * IN_DIM];
__device__ float g_Bt_im[(size_t)H_DIM * IN_DIM];
__device__ float g_Dt[(size_t)OUT_DIM * IN_DIM];
__device__ float g_nCim[(size_t)OUT_DIM * H_DIM];

// ---------------------------------------------------------------------------
// Helpers: cp.async + mma.sync (sm_80+ portable PTX)
// ---------------------------------------------------------------------------
__device__ __forceinline__ uint32_t smem_u32(const void* p) {
    uint32_t a;
    asm("{ .reg .u64 t; cvta.to.shared.u64 t, %1; cvt.u32.u64 %0, t; }"
        : "=r"(a) : "l"(p));
    return a;
}
__device__ __forceinline__ void cp_async16(uint32_t sa, const void* g) {
    asm volatile("cp.async.cg.shared.global [%0], [%1], 16;" :: "r"(sa), "l"(g));
}
#define CP_COMMIT() asm volatile("cp.async.commit_group;" ::: "memory")
#define CP_WAIT(n)  asm volatile("cp.async.wait_group %0;" :: "n"(n) : "memory")

#define MMA_TF32(c, a, b0, b1)                                              \
    asm volatile("mma.sync.aligned.m16n8k8.row.col.f32.tf32.tf32.f32 "      \
        "{%0,%1,%2,%3}, {%4,%5,%6,%7}, {%8,%9}, {%0,%1,%2,%3};"             \
        : "+f"((c)[0]), "+f"((c)[1]), "+f"((c)[2]), "+f"((c)[3])            \
        : "r"((a)[0]), "r"((a)[1]), "r"((a)[2]), "r"((a)[3]),               \
          "r"(b0), "r"(b1))

// Tile geometry: block 128x128, BK=32; smem tiles [128][32] pad stride 36
#define SSTRIDE 36
#define TILE_F (128 * SSTRIDE)
#define TILE_B (TILE_F * 4)

// Load a 128x32 fp32 tile (gmem row stride 1024) into smem tile. 256 thr.
__device__ __forceinline__ void load_tile(float* sdst, const float* __restrict__ g) {
    int t = threadIdx.x;
    #pragma unroll
    for (int j = 0; j < 4; ++j) {
        int c = t + 256 * j;
        int row = c >> 3, col = c & 7;
        cp_async16(smem_u32(sdst + row * SSTRIDE + col * 4),
                   g + (size_t)row * 1024 + col * 4);
    }
}

// ---------------------------------------------------------------------------
// Prep: lambda, gamma, lambda^CHUNK_L
// ---------------------------------------------------------------------------
__global__ void prep_kernel(const float* __restrict__ nu_log,
                            const float* __restrict__ theta_log,
                            const float* __restrict__ gamma_log) {
    int h = blockIdx.x * blockDim.x + threadIdx.x;
    if (h >= H_DIM) return;
    float mod = expf(-expf(nu_log[h]));
    float ph = expf(theta_log[h]);
    float lr = mod * cosf(ph);
    float li = mod * sinf(ph);
    g_lam_re[h] = lr;
    g_lam_im[h] = li;
    g_gam[h] = expf(gamma_log[h]);
    float pr = 1.f, pi = 0.f;
    #pragma unroll 4
    for (int i = 0; i < CHUNK_L; ++i) {
        float nr = pr * lr - pi * li;
        pi = pr * li + pi * lr;
        pr = nr;
    }
    g_lamL_re[h] = pr;
    g_lamL_im[h] = pi;
}

// ---------------------------------------------------------------------------
// Transpose 1024x1024: dst[j][i] = src[i][j] * (rowscale ? rowscale[i] : 1)
// ---------------------------------------------------------------------------
__global__ void transpose_kernel(const float* __restrict__ src,
                                 float* __restrict__ dst,
                                 const float* __restrict__ rowscale) {
    __shared__ float t[32][33];
    int bx = blockIdx.x * 32, by = blockIdx.y * 32;
    int x = threadIdx.x, y = threadIdx.y;
    #pragma unroll
    for (int r = 0; r < 32; r += 8) {
        int i = by + y + r;
        float s = rowscale ? rowscale[i] : 1.f;
        t[y + r][x] = src[(size_t)i * 1024 + bx + x] * s;
    }
    __syncthreads();
    #pragma unroll
    for (int r = 0; r < 32; r += 8)
        dst[(size_t)(bx + y + r) * 1024 + by + x] = t[x][y + r];
}

__global__ void negate_kernel(const float* __restrict__ src, float* __restrict__ dst) {
    size_t i = (size_t)(blockIdx.x * blockDim.x + threadIdx.x) * 4;
    float4 v = *reinterpret_cast<const float4*>(src + i);
    v.x = -v.x; v.y = -v.y; v.z = -v.z; v.w = -v.w;
    *reinterpret_cast<float4*>(dst + i) = v;
}

// ---------------------------------------------------------------------------
// Fused Bu GEMM: bu_re = x @ Bt_re^T, bu_im = x @ Bt_im^T
// 3-stage cp.async pipeline, 1 sync/chunk. 8 warps 2(m)x4(n), warp 64x32.
// ---------------------------------------------------------------------------
#define BU_SMEM (9 * TILE_B)   // 3 stages x (A,Bre,Bim) = 165888 B

__global__ void __launch_bounds__(256, 1)
bu_gemm_kernel(const float* __restrict__ X) {
    extern __shared__ float smem[];

    const int tid = threadIdx.x;
    const int lane = tid & 31, qid = lane >> 2, qtr = lane & 3;
    const int wid = tid >> 5, wm = wid & 1, wn = wid >> 1;
    const int bn = blockIdx.x * 128, bm = blockIdx.y * 128;

    const float* Ag = X + (size_t)bm * 1024;
    const float* Brg = g_Bt_re + (size_t)bn * 1024;
    const float* Big = g_Bt_im + (size_t)bn * 1024;

    float cre[4][4][4], cim[4][4][4];
    #pragma unroll
    for (int i = 0; i < 4; ++i)
        #pragma unroll
        for (int j = 0; j < 4; ++j)
            #pragma unroll
            for (int k = 0; k < 4; ++k) { cre[i][j][k] = 0.f; cim[i][j][k] = 0.f; }

    // prefetch stages 0,1
    #pragma unroll
    for (int p = 0; p < 2; ++p) {
        float* st = smem + p * 3 * TILE_F;
        load_tile(st, Ag + p * 32);
        load_tile(st + TILE_F, Brg + p * 32);
        load_tile(st + 2 * TILE_F, Big + p * 32);
        CP_COMMIT();
    }

    #pragma unroll 1
    for (int c = 0; c < 32; ++c) {
        if (c + 2 < 32) { CP_WAIT(1); } else { CP_WAIT(0); }
        __syncthreads();
        if (c + 2 < 32) {
            float* st = smem + ((c + 2) % 3) * 3 * TILE_F;
            load_tile(st, Ag + (c + 2) * 32);
            load_tile(st + TILE_F, Brg + (c + 2) * 32);
            load_tile(st + 2 * TILE_F, Big + (c + 2) * 32);
            CP_COMMIT();
        }
        const float* base = smem + (c % 3) * 3 * TILE_F;
        const float* a_s = base + (wm * 64 + qid) * SSTRIDE;
        const float* br_s = base + TILE_F + (wn * 32 + qid) * SSTRIDE;
        const float* bi_s = base + 2 * TILE_F + (wn * 32 + qid) * SSTRIDE;

        #pragma unroll
        for (int s = 0; s < 4; ++s) {
            int ko = s * 8 + qtr;
            uint32_t a[4][4];
            #pragma unroll
            for (int mt = 0; mt < 4; ++mt) {
                const float* ap = a_s + mt * 16 * SSTRIDE + ko;
                a[mt][0] = __float_as_uint(ap[0]);
                a[mt][1] = __float_as_uint(ap[8 * SSTRIDE]);
                a[mt][2] = __float_as_uint(ap[4]);
                a[mt][3] = __float_as_uint(ap[8 * SSTRIDE + 4]);
            }
            #pragma unroll
            for (int nt = 0; nt < 4; ++nt) {
                const float* bp = br_s + nt * 8 * SSTRIDE + ko;
                uint32_t br0 = __float_as_uint(bp[0]);
                uint32_t br1 = __float_as_uint(bp[4]);
                const float* bq = bi_s + nt * 8 * SSTRIDE + ko;
                uint32_t bi0 = __float_as_uint(bq[0]);
                uint32_t bi1 = __float_as_uint(bq[4]);
                #pragma unroll
                for (int mt = 0; mt < 4; ++mt) {
                    MMA_TF32(cre[mt][nt], a[mt], br0, br1);
                    MMA_TF32(cim[mt][nt], a[mt], bi0, bi1);
                }
            }
        }
    }

    #pragma unroll
    for (int mt = 0; mt < 4; ++mt) {
        int r = bm + wm * 64 + mt * 16 + qid;
        #pragma unroll
        for (int nt = 0; nt < 4; ++nt) {
            int cc = bn + wn * 32 + nt * 8 + 2 * qtr;
            *reinterpret_cast<float2*>(g_bu_re + (size_t)r * 1024 + cc) =
                make_float2(cre[mt][nt][0], cre[mt][nt][1]);
            *reinterpret_cast<float2*>(g_bu_re + (size_t)(r + 8) * 1024 + cc) =
                make_float2(cre[mt][nt][2], cre[mt][nt][3]);
            *reinterpret_cast<float2*>(g_bu_im + (size_t)r * 1024 + cc) =
                make_float2(cim[mt][nt][0], cim[mt][nt][1]);
            *reinterpret_cast<float2*>(g_bu_im + (size_t)(r + 8) * 1024 + cc) =
                make_float2(cim[mt][nt][2], cim[mt][nt][3]);
        }
    }
}

// ---------------------------------------------------------------------------
// Fused output GEMM: out = bu_re@C_re^T + bu_im@(-C_im)^T + x@Dt^T
// 3-stage pipeline, 1 sync/chunk, 2 blocks/SM.
// ---------------------------------------------------------------------------
#define OUT_SMEM (6 * TILE_B)   // 3 stages x (A,B) = 110592 B

__global__ void __launch_bounds__(256, 2)
out_gemm_kernel(const float* __restrict__ X, const float* __restrict__ Cre,
                float* __restrict__ out) {
    extern __shared__ float smem[];

    const int tid = threadIdx.x;
    const int lane = tid & 31, qid = lane >> 2, qtr = lane & 3;
    const int wid = tid >> 5, wm = wid & 1, wn = wid >> 1;
    const int bn = blockIdx.x * 128, bm = blockIdx.y * 128;

    const float* Aseg[3];
    const float* Bseg[3];
    Aseg[0] = g_bu_re + (size_t)bm * 1024;
    Aseg[1] = g_bu_im + (size_t)bm * 1024;
    Aseg[2] = X + (size_t)bm * 1024;
    Bseg[0] = Cre + (size_t)bn * 1024;
    Bseg[1] = g_nCim + (size_t)bn * 1024;
    Bseg[2] = g_Dt + (size_t)bn * 1024;

    float acc[4][4][4];
    #pragma unroll
    for (int i = 0; i < 4; ++i)
        #pragma unroll
        for (int j = 0; j < 4; ++j)
            #pragma unroll
            for (int k = 0; k < 4; ++k) acc[i][j][k] = 0.f;

    #pragma unroll
    for (int p = 0; p < 2; ++p) {
        float* st = smem + p * 2 * TILE_F;
        load_tile(st, Aseg[0] + p * 32);
        load_tile(st + TILE_F, Bseg[0] + p * 32);
        CP_COMMIT();
    }

    #pragma unroll 1
    for (int c = 0; c < 96; ++c) {
        if (c + 2 < 96) { CP_WAIT(1); } else { CP_WAIT(0); }
        __syncthreads();
        if (c + 2 < 96) {
            int nc = c + 2, s = nc >> 5, kk = (nc & 31) * 32;
            float* st = smem + (nc % 3) * 2 * TILE_F;
            load_tile(st, Aseg[s] + kk);
            load_tile(st + TILE_F, Bseg[s] + kk);
            CP_COMMIT();
        }
        const float* base = smem + (c % 3) * 2 * TILE_F;
        const float* a_s = base + (wm * 64 + qid) * SSTRIDE;
        const float* b_s = base + TILE_F + (wn * 32 + qid) * SSTRIDE;

        #pragma unroll
        for (int s = 0; s < 4; ++s) {
            int ko = s * 8 + qtr;
            uint32_t a[4][4];
            #pragma unroll
            for (int mt = 0; mt < 4; ++mt) {
                const float* ap = a_s + mt * 16 * SSTRIDE + ko;
                a[mt][0] = __float_as_uint(ap[0]);
                a[mt][1] = __float_as_uint(ap[8 * SSTRIDE]);
                a[mt][2] = __float_as_uint(ap[4]);
                a[mt][3] = __float_as_uint(ap[8 * SSTRIDE + 4]);
            }
            #pragma unroll
            for (int nt = 0; nt < 4; ++nt) {
                const float* bp = b_s + nt * 8 * SSTRIDE + ko;
                uint32_t b0 = __float_as_uint(bp[0]);
                uint32_t b1 = __float_as_uint(bp[4]);
                #pragma unroll
                for (int mt = 0; mt < 4; ++mt)
                    MMA_TF32(acc[mt][nt], a[mt], b0, b1);
            }
        }
    }

    #pragma unroll
    for (int mt = 0; mt < 4; ++mt) {
        int r = bm + wm * 64 + mt * 16 + qid;
        #pragma unroll
        for (int nt = 0; nt < 4; ++nt) {
            int cc = bn + wn * 32 + nt * 8 + 2 * qtr;
            *reinterpret_cast<float2*>(out + (size_t)r * 1024 + cc) =
                make_float2(acc[mt][nt][0], acc[mt][nt][1]);
            *reinterpret_cast<float2*>(out + (size_t)(r + 8) * 1024 + cc) =
                make_float2(acc[mt][nt][2], acc[mt][nt][3]);
        }
    }
}

// ---------------------------------------------------------------------------
// Scan pass 1 (read-only): per-chunk end state e_c = sum_j lam^{L-1-j} u_j
// One block per chunk; each thread handles 4 consecutive h (float4 loads).
// ---------------------------------------------------------------------------
__global__ void scan_sum_kernel() {
    int h4 = threadIdx.x * 4;
    int c = blockIdx.x;
    float4 lr4 = *reinterpret_cast<const float4*>(g_lam_re + h4);
    float4 li4 = *reinterpret_cast<const float4*>(g_lam_im + h4);
    float lr[4] = {lr4.x, lr4.y, lr4.z, lr4.w};
    float li[4] = {li4.x, li4.y, li4.z, li4.w};
    float sr[4] = {0, 0, 0, 0}, si[4] = {0, 0, 0, 0};
    const float* pre = g_bu_re + (size_t)c * CHUNK_L * H_DIM + h4;
    const float* pim = g_bu_im + (size_t)c * CHUNK_L * H_DIM + h4;
    #pragma unroll 4
    for (int j = 0; j < CHUNK_L; ++j) {
        float4 ur = *reinterpret_cast<const float4*>(pre + (size_t)j * H_DIM);
        float4 ui = *reinterpret_cast<const float4*>(pim + (size_t)j * H_DIM);
        const float urr[4] = {ur.x, ur.y, ur.z, ur.w};
        const float uii[4] = {ui.x, ui.y, ui.z, ui.w};
        #pragma unroll
        for (int q = 0; q < 4; ++q) {
            float nr = lr[q] * sr[q] - li[q] * si[q] + urr[q];
            float ni = lr[q] * si[q] + li[q] * sr[q] + uii[q];
            sr[q] = nr; si[q] = ni;
        }
    }
    *reinterpret_cast<float4*>(g_end_re + c * H_DIM + h4) =
        make_float4(sr[0], sr[1], sr[2], sr[3]);
    *reinterpret_cast<float4*>(g_end_im + c * H_DIM + h4) =
        make_float4(si[0], si[1], si[2], si[3]);
}

// ---------------------------------------------------------------------------
// Scan pass 2: carry chain across chunks (per h).
// ---------------------------------------------------------------------------
__global__ void scan_carry_kernel() {
    int h = blockIdx.x * blockDim.x + threadIdx.x;
    float Lr = g_lamL_re[h], Li = g_lamL_im[h];
    float cr = 0.f, ci = 0.f;
    for (int k = 0; k < NCHUNK; ++k) {
        g_carry_re[k * H_DIM + h] = cr;
        g_carry_im[k * H_DIM + h] = ci;
        float er = g_end_re[k * H_DIM + h];
        float ei = g_end_im[k * H_DIM + h];
        float nr = Lr * cr - Li * ci + er;
        float ni = Lr * ci + Li * cr + ei;
        cr = nr; ci = ni;
    }
}

// ---------------------------------------------------------------------------
// Scan pass 3: full scan seeded with carry; writes final hidden states.
// ---------------------------------------------------------------------------
__global__ void scan_full_kernel() {
    int h4 = threadIdx.x * 4;
    int c = blockIdx.x;
    float4 lr4 = *reinterpret_cast<const float4*>(g_lam_re + h4);
    float4 li4 = *reinterpret_cast<const float4*>(g_lam_im + h4);
    float4 cr4 = *reinterpret_cast<const float4*>(g_carry_re + c * H_DIM + h4);
    float4 ci4 = *reinterpret_cast<const float4*>(g_carry_im + c * H_DIM + h4);
    float lr[4] = {lr4.x, lr4.y, lr4.z, lr4.w};
    float li[4] = {li4.x, li4.y, li4.z, li4.w};
    float sr[4] = {cr4.x, cr4.y, cr4.z, cr4.w};
    float si[4] = {ci4.x, ci4.y, ci4.z, ci4.w};
    float* pre = g_bu_re + (size_t)c * CHUNK_L * H_DIM + h4;
    float* pim = g_bu_im + (size_t)c * CHUNK_L * H_DIM + h4;
    #pragma unroll 4
    for (int j = 0; j < CHUNK_L; ++j) {
        float4 ur = *reinterpret_cast<float4*>(pre + (size_t)j * H_DIM);
        float4 ui = *reinterpret_cast<float4*>(pim + (size_t)j * H_DIM);
        const float urr[4] = {ur.x, ur.y, ur.z, ur.w};
        const float uii[4] = {ui.x, ui.y, ui.z, ui.w};
        #pragma unroll
        for (int q = 0; q < 4; ++q) {
            float nr = lr[q] * sr[q] - li[q] * si[q] + urr[q];
            float ni = lr[q] * si[q] + li[q] * sr[q] + uii[q];
            sr[q] = nr; si[q] = ni;
        }
        *reinterpret_cast<float4*>(pre + (size_t)j * H_DIM) =
            make_float4(sr[0], sr[1], sr[2], sr[3]);
        *reinterpret_cast<float4*>(pim + (size_t)j * H_DIM) =
            make_float4(si[0], si[1], si[2], si[3]);
    }
}

// ---------------------------------------------------------------------------
// Launch
// ---------------------------------------------------------------------------
extern "C" void kernel_launch(void* const* d_in, const int* in_sizes, int n_in,
                              void* d_out, int out_size) {
    const float* x    = (const float*)d_in[0];
    const float* nu   = (const float*)d_in[1];
    const float* th   = (const float*)d_in[2];
    const float* ga   = (const float*)d_in[3];
    const float* B_re = (const float*)d_in[4];
    const float* B_im = (const float*)d_in[5];
    const float* C_re = (const float*)d_in[6];
    const float* C_im = (const float*)d_in[7];
    const float* Dm   = (const float*)d_in[8];
    float* out = (float*)d_out;

    float *bt_re, *bt_im, *dt, *ncim, *gam;
    cudaGetSymbolAddress((void**)&bt_re, g_Bt_re);
    cudaGetSymbolAddress((void**)&bt_im, g_Bt_im);
    cudaGetSymbolAddress((void**)&dt, g_Dt);
    cudaGetSymbolAddress((void**)&ncim, g_nCim);
    cudaGetSymbolAddress((void**)&gam, g_gam);

    cudaFuncSetAttribute(bu_gemm_kernel, cudaFuncAttributeMaxDynamicSharedMemorySize, BU_SMEM);
    cudaFuncSetAttribute(out_gemm_kernel, cudaFuncAttributeMaxDynamicSharedMemorySize, OUT_SMEM);

    prep_kernel<<<H_DIM / 256, 256>>>(nu, th, ga);

    dim3 tgrid(32, 32), tblk(32, 8);
    transpose_kernel<<<tgrid, tblk>>>(B_re, bt_re, gam);
    transpose_kernel<<<tgrid, tblk>>>(B_im, bt_im, gam);
    transpose_kernel<<<tgrid, tblk>>>(Dm, dt, nullptr);
    negate_kernel<<<(OUT_DIM * H_DIM / 4) / 256, 256>>>(C_im, ncim);

    dim3 ggrid(H_DIM / 128, T_LEN / 128);  // (8, 128)
    bu_gemm_kernel<<<ggrid, 256, BU_SMEM>>>(x);

    scan_sum_kernel<<<NCHUNK, 256>>>();
    scan_carry_kernel<<<H_DIM / 256, 256>>>();
    scan_full_kernel<<<NCHUNK, 256>>>();

    out_gemm_kernel<<<ggrid, 256, OUT_SMEM>>>(x, C_re, out);
}

// round 7
// speedup vs baseline: 3.7041x; 1.0074x over previous
#include <cuda_runtime.h>
#include <cstdint>
#include <math.h>

// Problem constants
#define T_LEN 16384
#define H_DIM 1024
#define IN_DIM 1024
#define OUT_DIM 1024
#define NCHUNK 128
#define CHUNK_L 128

// ---------------------------------------------------------------------------
// Scratch (device globals: allocation-free kernel_launch)
// ---------------------------------------------------------------------------
__device__ float g_bu_re[(size_t)T_LEN * H_DIM];
__device__ float g_bu_im[(size_t)T_LEN * H_DIM];
__device__ float g_end_re[NCHUNK * H_DIM];
__device__ float g_end_im[NCHUNK * H_DIM];
__device__ float g_carry_re[NCHUNK * H_DIM];
__device__ float g_carry_im[NCHUNK * H_DIM];
__device__ float g_lam_re[H_DIM];
__device__ float g_lam_im[H_DIM];
__device__ float g_lamL_re[H_DIM];
__device__ float g_lamL_im[H_DIM];
__device__ float g_gam[H_DIM];
// Preprocessed weights ([N][K] row-major, K-contiguous)
__device__ float g_Bt_re[(size_t)H_DIM * IN_DIM];
__device__ float g_Bt_im[(size_t)H_DIM * IN_DIM];
__device__ float g_Dt[(size_t)OUT_DIM * IN_DIM];
__device__ float g_nCim[(size_t)OUT_DIM * H_DIM];

// ---------------------------------------------------------------------------
// Helpers: cp.async + mma.sync (sm_80+ portable PTX)
// ---------------------------------------------------------------------------
__device__ __forceinline__ uint32_t smem_u32(const void* p) {
    uint32_t a;
    asm("{ .reg .u64 t; cvta.to.shared.u64 t, %1; cvt.u32.u64 %0, t; }"
        : "=r"(a) : "l"(p));
    return a;
}
__device__ __forceinline__ void cp_async16(uint32_t sa, const void* g) {
    asm volatile("cp.async.cg.shared.global [%0], [%1], 16;" :: "r"(sa), "l"(g));
}
#define CP_COMMIT() asm volatile("cp.async.commit_group;" ::: "memory")
#define CP_WAIT(n)  asm volatile("cp.async.wait_group %0;" :: "n"(n) : "memory")

#define MMA_TF32(c, a, b0, b1)                                              \
    asm volatile("mma.sync.aligned.m16n8k8.row.col.f32.tf32.tf32.f32 "      \
        "{%0,%1,%2,%3}, {%4,%5,%6,%7}, {%8,%9}, {%0,%1,%2,%3};"             \
        : "+f"((c)[0]), "+f"((c)[1]), "+f"((c)[2]), "+f"((c)[3])            \
        : "r"((a)[0]), "r"((a)[1]), "r"((a)[2]), "r"((a)[3]),               \
          "r"(b0), "r"(b1))

// Tile geometry: block 128x128, BK=32; smem tiles [128][32] pad stride 36
#define SSTRIDE 36
#define TILE_F (128 * SSTRIDE)
#define TILE_B (TILE_F * 4)

// Load a 128x32 fp32 tile (gmem row stride 1024) into smem tile. 256 thr.
__device__ __forceinline__ void load_tile(float* sdst, const float* __restrict__ g) {
    int t = threadIdx.x;
    #pragma unroll
    for (int j = 0; j < 4; ++j) {
        int c = t + 256 * j;
        int row = c >> 3, col = c & 7;
        cp_async16(smem_u32(sdst + row * SSTRIDE + col * 4),
                   g + (size_t)row * 1024 + col * 4);
    }
}

// ---------------------------------------------------------------------------
// Prep: lambda, gamma, lambda^CHUNK_L
// ---------------------------------------------------------------------------
__global__ void prep_kernel(const float* __restrict__ nu_log,
                            const float* __restrict__ theta_log,
                            const float* __restrict__ gamma_log) {
    int h = blockIdx.x * blockDim.x + threadIdx.x;
    if (h >= H_DIM) return;
    float mod = expf(-expf(nu_log[h]));
    float ph = expf(theta_log[h]);
    float lr = mod * cosf(ph);
    float li = mod * sinf(ph);
    g_lam_re[h] = lr;
    g_lam_im[h] = li;
    g_gam[h] = expf(gamma_log[h]);
    float pr = 1.f, pi = 0.f;
    #pragma unroll 4
    for (int i = 0; i < CHUNK_L; ++i) {
        float nr = pr * lr - pi * li;
        pi = pr * li + pi * lr;
        pr = nr;
    }
    g_lamL_re[h] = pr;
    g_lamL_im[h] = pi;
}

// ---------------------------------------------------------------------------
// Transpose 1024x1024: dst[j][i] = src[i][j] * (rowscale ? rowscale[i] : 1)
// ---------------------------------------------------------------------------
__global__ void transpose_kernel(const float* __restrict__ src,
                                 float* __restrict__ dst,
                                 const float* __restrict__ rowscale) {
    __shared__ float t[32][33];
    int bx = blockIdx.x * 32, by = blockIdx.y * 32;
    int x = threadIdx.x, y = threadIdx.y;
    #pragma unroll
    for (int r = 0; r < 32; r += 8) {
        int i = by + y + r;
        float s = rowscale ? rowscale[i] : 1.f;
        t[y + r][x] = src[(size_t)i * 1024 + bx + x] * s;
    }
    __syncthreads();
    #pragma unroll
    for (int r = 0; r < 32; r += 8)
        dst[(size_t)(bx + y + r) * 1024 + by + x] = t[x][y + r];
}

__global__ void negate_kernel(const float* __restrict__ src, float* __restrict__ dst) {
    size_t i = (size_t)(blockIdx.x * blockDim.x + threadIdx.x) * 4;
    float4 v = *reinterpret_cast<const float4*>(src + i);
    v.x = -v.x; v.y = -v.y; v.z = -v.z; v.w = -v.w;
    *reinterpret_cast<float4*>(dst + i) = v;
}

// ---------------------------------------------------------------------------
// Bu GEMM as wide-N: grid (16, 128). bx<8 -> Bt_re/bu_re, else Bt_im/bu_im.
// 3-stage pipeline, 1 sync/chunk, 2 blocks/SM.
// ---------------------------------------------------------------------------
#define GEMM_SMEM (6 * TILE_B)   // 3 stages x (A,B) = 110592 B

__global__ void __launch_bounds__(256, 2)
bu_gemm_kernel(const float* __restrict__ X) {
    extern __shared__ float smem[];

    const int tid = threadIdx.x;
    const int lane = tid & 31, qid = lane >> 2, qtr = lane & 3;
    const int wid = tid >> 5, wm = wid & 1, wn = wid >> 1;
    const int bxi = blockIdx.x;
    const int bn = (bxi & 7) * 128, bm = blockIdx.y * 128;

    const float* Ag = X + (size_t)bm * 1024;
    const float* Bg;
    float* Og;
    if (bxi < 8) { Bg = g_Bt_re + (size_t)bn * 1024; Og = g_bu_re; }
    else         { Bg = g_Bt_im + (size_t)bn * 1024; Og = g_bu_im; }

    float acc[4][4][4];
    #pragma unroll
    for (int i = 0; i < 4; ++i)
        #pragma unroll
        for (int j = 0; j < 4; ++j)
            #pragma unroll
            for (int k = 0; k < 4; ++k) acc[i][j][k] = 0.f;

    #pragma unroll
    for (int p = 0; p < 2; ++p) {
        float* st = smem + p * 2 * TILE_F;
        load_tile(st, Ag + p * 32);
        load_tile(st + TILE_F, Bg + p * 32);
        CP_COMMIT();
    }

    #pragma unroll 1
    for (int c = 0; c < 32; ++c) {
        if (c + 2 < 32) { CP_WAIT(1); } else { CP_WAIT(0); }
        __syncthreads();
        if (c + 2 < 32) {
            float* st = smem + ((c + 2) % 3) * 2 * TILE_F;
            load_tile(st, Ag + (c + 2) * 32);
            load_tile(st + TILE_F, Bg + (c + 2) * 32);
            CP_COMMIT();
        }
        const float* base = smem + (c % 3) * 2 * TILE_F;
        const float* a_s = base + (wm * 64 + qid) * SSTRIDE;
        const float* b_s = base + TILE_F + (wn * 32 + qid) * SSTRIDE;

        #pragma unroll
        for (int s = 0; s < 4; ++s) {
            int ko = s * 8 + qtr;
            uint32_t a[4][4];
            #pragma unroll
            for (int mt = 0; mt < 4; ++mt) {
                const float* ap = a_s + mt * 16 * SSTRIDE + ko;
                a[mt][0] = __float_as_uint(ap[0]);
                a[mt][1] = __float_as_uint(ap[8 * SSTRIDE]);
                a[mt][2] = __float_as_uint(ap[4]);
                a[mt][3] = __float_as_uint(ap[8 * SSTRIDE + 4]);
            }
            #pragma unroll
            for (int nt = 0; nt < 4; ++nt) {
                const float* bp = b_s + nt * 8 * SSTRIDE + ko;
                uint32_t b0 = __float_as_uint(bp[0]);
                uint32_t b1 = __float_as_uint(bp[4]);
                #pragma unroll
                for (int mt = 0; mt < 4; ++mt)
                    MMA_TF32(acc[mt][nt], a[mt], b0, b1);
            }
        }
    }

    #pragma unroll
    for (int mt = 0; mt < 4; ++mt) {
        int r = bm + wm * 64 + mt * 16 + qid;
        #pragma unroll
        for (int nt = 0; nt < 4; ++nt) {
            int cc = bn + wn * 32 + nt * 8 + 2 * qtr;
            *reinterpret_cast<float2*>(Og + (size_t)r * 1024 + cc) =
                make_float2(acc[mt][nt][0], acc[mt][nt][1]);
            *reinterpret_cast<float2*>(Og + (size_t)(r + 8) * 1024 + cc) =
                make_float2(acc[mt][nt][2], acc[mt][nt][3]);
        }
    }
}

// ---------------------------------------------------------------------------
// Fused output GEMM: out = bu_re@C_re^T + bu_im@(-C_im)^T + x@Dt^T
// 3-stage pipeline, 1 sync/chunk, 2 blocks/SM.
// ---------------------------------------------------------------------------
__global__ void __launch_bounds__(256, 2)
out_gemm_kernel(const float* __restrict__ X, const float* __restrict__ Cre,
                float* __restrict__ out) {
    extern __shared__ float smem[];

    const int tid = threadIdx.x;
    const int lane = tid & 31, qid = lane >> 2, qtr = lane & 3;
    const int wid = tid >> 5, wm = wid & 1, wn = wid >> 1;
    const int bn = blockIdx.x * 128, bm = blockIdx.y * 128;

    const float* Aseg[3];
    const float* Bseg[3];
    Aseg[0] = g_bu_re + (size_t)bm * 1024;
    Aseg[1] = g_bu_im + (size_t)bm * 1024;
    Aseg[2] = X + (size_t)bm * 1024;
    Bseg[0] = Cre + (size_t)bn * 1024;
    Bseg[1] = g_nCim + (size_t)bn * 1024;
    Bseg[2] = g_Dt + (size_t)bn * 1024;

    float acc[4][4][4];
    #pragma unroll
    for (int i = 0; i < 4; ++i)
        #pragma unroll
        for (int j = 0; j < 4; ++j)
            #pragma unroll
            for (int k = 0; k < 4; ++k) acc[i][j][k] = 0.f;

    #pragma unroll
    for (int p = 0; p < 2; ++p) {
        float* st = smem + p * 2 * TILE_F;
        load_tile(st, Aseg[0] + p * 32);
        load_tile(st + TILE_F, Bseg[0] + p * 32);
        CP_COMMIT();
    }

    #pragma unroll 1
    for (int c = 0; c < 96; ++c) {
        if (c + 2 < 96) { CP_WAIT(1); } else { CP_WAIT(0); }
        __syncthreads();
        if (c + 2 < 96) {
            int nc = c + 2, s = nc >> 5, kk = (nc & 31) * 32;
            float* st = smem + (nc % 3) * 2 * TILE_F;
            load_tile(st, Aseg[s] + kk);
            load_tile(st + TILE_F, Bseg[s] + kk);
            CP_COMMIT();
        }
        const float* base = smem + (c % 3) * 2 * TILE_F;
        const float* a_s = base + (wm * 64 + qid) * SSTRIDE;
        const float* b_s = base + TILE_F + (wn * 32 + qid) * SSTRIDE;

        #pragma unroll
        for (int s = 0; s < 4; ++s) {
            int ko = s * 8 + qtr;
            uint32_t a[4][4];
            #pragma unroll
            for (int mt = 0; mt < 4; ++mt) {
                const float* ap = a_s + mt * 16 * SSTRIDE + ko;
                a[mt][0] = __float_as_uint(ap[0]);
                a[mt][1] = __float_as_uint(ap[8 * SSTRIDE]);
                a[mt][2] = __float_as_uint(ap[4]);
                a[mt][3] = __float_as_uint(ap[8 * SSTRIDE + 4]);
            }
            #pragma unroll
            for (int nt = 0; nt < 4; ++nt) {
                const float* bp = b_s + nt * 8 * SSTRIDE + ko;
                uint32_t b0 = __float_as_uint(bp[0]);
                uint32_t b1 = __float_as_uint(bp[4]);
                #pragma unroll
                for (int mt = 0; mt < 4; ++mt)
                    MMA_TF32(acc[mt][nt], a[mt], b0, b1);
            }
        }
    }

    #pragma unroll
    for (int mt = 0; mt < 4; ++mt) {
        int r = bm + wm * 64 + mt * 16 + qid;
        #pragma unroll
        for (int nt = 0; nt < 4; ++nt) {
            int cc = bn + wn * 32 + nt * 8 + 2 * qtr;
            *reinterpret_cast<float2*>(out + (size_t)r * 1024 + cc) =
                make_float2(acc[mt][nt][0], acc[mt][nt][1]);
            *reinterpret_cast<float2*>(out + (size_t)(r + 8) * 1024 + cc) =
                make_float2(acc[mt][nt][2], acc[mt][nt][3]);
        }
    }
}

// ---------------------------------------------------------------------------
// Scan pass 1 (read-only): per-chunk end state. grid (2, NCHUNK), float2/thr.
// ---------------------------------------------------------------------------
__global__ void scan_sum_kernel() {
    int h2 = blockIdx.x * 512 + threadIdx.x * 2;
    int c = blockIdx.y;
    float2 lr2 = *reinterpret_cast<const float2*>(g_lam_re + h2);
    float2 li2 = *reinterpret_cast<const float2*>(g_lam_im + h2);
    float lr[2] = {lr2.x, lr2.y}, li[2] = {li2.x, li2.y};
    float sr[2] = {0, 0}, si[2] = {0, 0};
    const float* pre = g_bu_re + (size_t)c * CHUNK_L * H_DIM + h2;
    const float* pim = g_bu_im + (size_t)c * CHUNK_L * H_DIM + h2;
    #pragma unroll 4
    for (int j = 0; j < CHUNK_L; ++j) {
        float2 ur = *reinterpret_cast<const float2*>(pre + (size_t)j * H_DIM);
        float2 ui = *reinterpret_cast<const float2*>(pim + (size_t)j * H_DIM);
        const float urr[2] = {ur.x, ur.y};
        const float uii[2] = {ui.x, ui.y};
        #pragma unroll
        for (int q = 0; q < 2; ++q) {
            float nr = lr[q] * sr[q] - li[q] * si[q] + urr[q];
            float ni = lr[q] * si[q] + li[q] * sr[q] + uii[q];
            sr[q] = nr; si[q] = ni;
        }
    }
    *reinterpret_cast<float2*>(g_end_re + c * H_DIM + h2) = make_float2(sr[0], sr[1]);
    *reinterpret_cast<float2*>(g_end_im + c * H_DIM + h2) = make_float2(si[0], si[1]);
}

// ---------------------------------------------------------------------------
// Scan pass 2: carry chain across chunks (per h).
// ---------------------------------------------------------------------------
__global__ void scan_carry_kernel() {
    int h = blockIdx.x * blockDim.x + threadIdx.x;
    float Lr = g_lamL_re[h], Li = g_lamL_im[h];
    float cr = 0.f, ci = 0.f;
    for (int k = 0; k < NCHUNK; ++k) {
        g_carry_re[k * H_DIM + h] = cr;
        g_carry_im[k * H_DIM + h] = ci;
        float er = g_end_re[k * H_DIM + h];
        float ei = g_end_im[k * H_DIM + h];
        float nr = Lr * cr - Li * ci + er;
        float ni = Lr * ci + Li * cr + ei;
        cr = nr; ci = ni;
    }
}

// ---------------------------------------------------------------------------
// Scan pass 3: full scan seeded with carry; writes final hidden states.
// grid (2, NCHUNK), float2 per thread.
// ---------------------------------------------------------------------------
__global__ void scan_full_kernel() {
    int h2 = blockIdx.x * 512 + threadIdx.x * 2;
    int c = blockIdx.y;
    float2 lr2 = *reinterpret_cast<const float2*>(g_lam_re + h2);
    float2 li2 = *reinterpret_cast<const float2*>(g_lam_im + h2);
    float2 cr2 = *reinterpret_cast<const float2*>(g_carry_re + c * H_DIM + h2);
    float2 ci2 = *reinterpret_cast<const float2*>(g_carry_im + c * H_DIM + h2);
    float lr[2] = {lr2.x, lr2.y}, li[2] = {li2.x, li2.y};
    float sr[2] = {cr2.x, cr2.y}, si[2] = {ci2.x, ci2.y};
    float* pre = g_bu_re + (size_t)c * CHUNK_L * H_DIM + h2;
    float* pim = g_bu_im + (size_t)c * CHUNK_L * H_DIM + h2;
    #pragma unroll 4
    for (int j = 0; j < CHUNK_L; ++j) {
        float2 ur = *reinterpret_cast<float2*>(pre + (size_t)j * H_DIM);
        float2 ui = *reinterpret_cast<float2*>(pim + (size_t)j * H_DIM);
        const float urr[2] = {ur.x, ur.y};
        const float uii[2] = {ui.x, ui.y};
        #pragma unroll
        for (int q = 0; q < 2; ++q) {
            float nr = lr[q] * sr[q] - li[q] * si[q] + urr[q];
            float ni = lr[q] * si[q] + li[q] * sr[q] + uii[q];
            sr[q] = nr; si[q] = ni;
        }
        *reinterpret_cast<float2*>(pre + (size_t)j * H_DIM) = make_float2(sr[0], sr[1]);
        *reinterpret_cast<float2*>(pim + (size_t)j * H_DIM) = make_float2(si[0], si[1]);
    }
}

// ---------------------------------------------------------------------------
// Launch
// ---------------------------------------------------------------------------
extern "C" void kernel_launch(void* const* d_in, const int* in_sizes, int n_in,
                              void* d_out, int out_size) {
    const float* x    = (const float*)d_in[0];
    const float* nu   = (const float*)d_in[1];
    const float* th   = (const float*)d_in[2];
    const float* ga   = (const float*)d_in[3];
    const float* B_re = (const float*)d_in[4];
    const float* B_im = (const float*)d_in[5];
    const float* C_re = (const float*)d_in[6];
    const float* C_im = (const float*)d_in[7];
    const float* Dm   = (const float*)d_in[8];
    float* out = (float*)d_out;

    float *bt_re, *bt_im, *dt, *ncim, *gam;
    cudaGetSymbolAddress((void**)&bt_re, g_Bt_re);
    cudaGetSymbolAddress((void**)&bt_im, g_Bt_im);
    cudaGetSymbolAddress((void**)&dt, g_Dt);
    cudaGetSymbolAddress((void**)&ncim, g_nCim);
    cudaGetSymbolAddress((void**)&gam, g_gam);

    cudaFuncSetAttribute(bu_gemm_kernel, cudaFuncAttributeMaxDynamicSharedMemorySize, GEMM_SMEM);
    cudaFuncSetAttribute(out_gemm_kernel, cudaFuncAttributeMaxDynamicSharedMemorySize, GEMM_SMEM);

    prep_kernel<<<H_DIM / 256, 256>>>(nu, th, ga);

    dim3 tgrid(32, 32), tblk(32, 8);
    transpose_kernel<<<tgrid, tblk>>>(B_re, bt_re, gam);
    transpose_kernel<<<tgrid, tblk>>>(B_im, bt_im, gam);
    transpose_kernel<<<tgrid, tblk>>>(Dm, dt, nullptr);
    negate_kernel<<<(OUT_DIM * H_DIM / 4) / 256, 256>>>(C_im, ncim);

    bu_gemm_kernel<<<dim3(16, T_LEN / 128), 256, GEMM_SMEM>>>(x);

    scan_sum_kernel<<<dim3(2, NCHUNK), 256>>>();
    scan_carry_kernel<<<H_DIM / 256, 256>>>();
    scan_full_kernel<<<dim3(2, NCHUNK), 256>>>();

    out_gemm_kernel<<<dim3(8, T_LEN / 128), 256, GEMM_SMEM>>>(x, C_re, out);
}

// round 8
// speedup vs baseline: 6.7048x; 1.8101x over previous
#include <cuda_runtime.h>
#include <cuda_fp16.h>
#include <cstdint>
#include <math.h>

// Problem constants
#define T_LEN 16384
#define H_DIM 1024
#define IN_DIM 1024
#define OUT_DIM 1024
#define NCHUNK 128
#define CHUNK_L 128

// ---------------------------------------------------------------------------
// Scratch (device globals: allocation-free kernel_launch)
// ---------------------------------------------------------------------------
__device__ float g_bu_re[(size_t)T_LEN * H_DIM];    // fp32: exact scan input
__device__ float g_bu_im[(size_t)T_LEN * H_DIM];
__device__ __half g_h_re[(size_t)T_LEN * H_DIM];    // fp16 hidden states
__device__ __half g_h_im[(size_t)T_LEN * H_DIM];
__device__ __half g_x_h[(size_t)T_LEN * IN_DIM];    // fp16 inputs
__device__ float g_end_re[NCHUNK * H_DIM];
__device__ float g_end_im[NCHUNK * H_DIM];
__device__ float g_carry_re[NCHUNK * H_DIM];
__device__ float g_carry_im[NCHUNK * H_DIM];
__device__ float g_lam_re[H_DIM];
__device__ float g_lam_im[H_DIM];
__device__ float g_lamL_re[H_DIM];
__device__ float g_lamL_im[H_DIM];
__device__ float g_gam[H_DIM];
// fp16 preprocessed weights ([N][K] row-major, K-contiguous)
__device__ __half g_Bt_re[(size_t)H_DIM * IN_DIM];
__device__ __half g_Bt_im[(size_t)H_DIM * IN_DIM];
__device__ __half g_Dt[(size_t)OUT_DIM * IN_DIM];
__device__ __half g_Cre[(size_t)OUT_DIM * H_DIM];
__device__ __half g_nCim[(size_t)OUT_DIM * H_DIM];

// ---------------------------------------------------------------------------
// Helpers: cp.async + ldmatrix + fp16 mma (all sm_80+ portable PTX)
// ---------------------------------------------------------------------------
__device__ __forceinline__ uint32_t smem_u32(const void* p) {
    uint32_t a;
    asm("{ .reg .u64 t; cvta.to.shared.u64 t, %1; cvt.u32.u64 %0, t; }"
        : "=r"(a) : "l"(p));
    return a;
}
__device__ __forceinline__ void cp_async16(uint32_t sa, const void* g) {
    asm volatile("cp.async.cg.shared.global [%0], [%1], 16;" :: "r"(sa), "l"(g));
}
#define CP_COMMIT() asm volatile("cp.async.commit_group;" ::: "memory")
#define CP_WAIT(n)  asm volatile("cp.async.wait_group %0;" :: "n"(n) : "memory")

#define LDMX4(r, addr)                                                       \
    asm volatile("ldmatrix.sync.aligned.m8n8.x4.shared.b16 "                 \
        "{%0,%1,%2,%3}, [%4];"                                               \
        : "=r"((r)[0]), "=r"((r)[1]), "=r"((r)[2]), "=r"((r)[3])             \
        : "r"(addr))

#define MMA_F16(c, a, b0, b1)                                                \
    asm volatile("mma.sync.aligned.m16n8k16.row.col.f32.f16.f16.f32 "        \
        "{%0,%1,%2,%3}, {%4,%5,%6,%7}, {%8,%9}, {%0,%1,%2,%3};"              \
        : "+f"((c)[0]), "+f"((c)[1]), "+f"((c)[2]), "+f"((c)[3])             \
        : "r"((a)[0]), "r"((a)[1]), "r"((a)[2]), "r"((a)[3]),                \
          "r"(b0), "r"(b1))

// fp16 tile: 128 rows x 32 halfs (64 B/row), XOR swizzle on 16B units:
// phys_unit = u ^ ((row>>1)&3)  -> ldmatrix phases are bank-conflict-free.
#define HTILE_B 8192
#define STAGE_B (2 * HTILE_B)      // A + B tile per stage
#define GEMM_SMEM (3 * STAGE_B)    // 3 stages = 49152 B

// Load a 128x32 fp16 tile (gmem row stride 1024 halfs). 256 threads.
__device__ __forceinline__ void load_tile_h(char* sdst, const __half* __restrict__ g) {
    int t = threadIdx.x;
    #pragma unroll
    for (int j = 0; j < 2; ++j) {
        int q = t + 256 * j;              // 0..511 16B-units
        int row = q >> 2, u = q & 3;
        int pu = u ^ ((row >> 1) & 3);
        cp_async16(smem_u32(sdst + row * 64 + pu * 16),
                   g + (size_t)row * 1024 + u * 8);
    }
}

// ---------------------------------------------------------------------------
// Prep: lambda, gamma, lambda^CHUNK_L
// ---------------------------------------------------------------------------
__global__ void prep_kernel(const float* __restrict__ nu_log,
                            const float* __restrict__ theta_log,
                            const float* __restrict__ gamma_log) {
    int h = blockIdx.x * blockDim.x + threadIdx.x;
    if (h >= H_DIM) return;
    float mod = expf(-expf(nu_log[h]));
    float ph = expf(theta_log[h]);
    float lr = mod * cosf(ph);
    float li = mod * sinf(ph);
    g_lam_re[h] = lr;
    g_lam_im[h] = li;
    g_gam[h] = expf(gamma_log[h]);
    float pr = 1.f, pi = 0.f;
    #pragma unroll 4
    for (int i = 0; i < CHUNK_L; ++i) {
        float nr = pr * lr - pi * li;
        pi = pr * li + pi * lr;
        pr = nr;
    }
    g_lamL_re[h] = pr;
    g_lamL_im[h] = pi;
}

// ---------------------------------------------------------------------------
// Transpose 1024x1024 -> fp16: dst[j][i] = h(src[i][j] * scale_i)
// ---------------------------------------------------------------------------
__global__ void transpose_kernel(const float* __restrict__ src,
                                 __half* __restrict__ dst,
                                 const float* __restrict__ rowscale) {
    __shared__ float t[32][33];
    int bx = blockIdx.x * 32, by = blockIdx.y * 32;
    int x = threadIdx.x, y = threadIdx.y;
    #pragma unroll
    for (int r = 0; r < 32; r += 8) {
        int i = by + y + r;
        float s = rowscale ? rowscale[i] : 1.f;
        t[y + r][x] = src[(size_t)i * 1024 + bx + x] * s;
    }
    __syncthreads();
    #pragma unroll
    for (int r = 0; r < 32; r += 8)
        dst[(size_t)(bx + y + r) * 1024 + by + x] = __float2half(t[x][y + r]);
}

// fp32 -> fp16 convert with scale; 4 elements/thread
__global__ void convert_kernel(const float* __restrict__ src,
                               __half* __restrict__ dst, float scale) {
    size_t i = (size_t)(blockIdx.x * blockDim.x + threadIdx.x) * 4;
    float4 v = *reinterpret_cast<const float4*>(src + i);
    *reinterpret_cast<__half2*>(dst + i) = __floats2half2_rn(v.x * scale, v.y * scale);
    *reinterpret_cast<__half2*>(dst + i + 2) = __floats2half2_rn(v.z * scale, v.w * scale);
}

// ---------------------------------------------------------------------------
// Shared GEMM inner machinery (fp16 ldmatrix + m16n8k16)
// Block tile 128x128, BK=32, 8 warps as 2(m) x 4(n), warp tile 64x32.
// ---------------------------------------------------------------------------
struct FragCtx {
    uint32_t aoff[4], asw[4];
    uint32_t boff[2], bsw[2];
    int kmA, kmB;
};

__device__ __forceinline__ void init_frag_ctx(FragCtx& fc, int lane, int wm, int wn) {
    int mx = lane >> 3, rr = lane & 7;
    fc.kmA = mx >> 1;
    #pragma unroll
    for (int mt = 0; mt < 4; ++mt) {
        int row = wm * 64 + mt * 16 + 8 * (mx & 1) + rr;
        fc.aoff[mt] = row * 64;
        fc.asw[mt] = (row >> 1) & 3;
    }
    fc.kmB = (lane >> 3) & 1;
    #pragma unroll
    for (int p = 0; p < 2; ++p) {
        int row = wn * 32 + p * 16 + 8 * (lane >> 4) + rr;
        fc.boff[p] = row * 64;
        fc.bsw[p] = (row >> 1) & 3;
    }
}

__device__ __forceinline__ void gemm_chunk(float acc[4][4][4], const FragCtx& fc,
                                           uint32_t A32, uint32_t B32) {
    #pragma unroll
    for (int s = 0; s < 2; ++s) {
        uint32_t a[4][4];
        #pragma unroll
        for (int mt = 0; mt < 4; ++mt)
            LDMX4(a[mt], A32 + fc.aoff[mt] + ((uint32_t)((2 * s + fc.kmA) ^ fc.asw[mt]) << 4));
        uint32_t bb[2][4];
        #pragma unroll
        for (int p = 0; p < 2; ++p)
            LDMX4(bb[p], B32 + fc.boff[p] + ((uint32_t)((2 * s + fc.kmB) ^ fc.bsw[p]) << 4));
        #pragma unroll
        for (int nt = 0; nt < 4; ++nt) {
            uint32_t b0 = bb[nt >> 1][(nt & 1) * 2];
            uint32_t b1 = bb[nt >> 1][(nt & 1) * 2 + 1];
            #pragma unroll
            for (int mt = 0; mt < 4; ++mt)
                MMA_F16(acc[mt][nt], a[mt], b0, b1);
        }
    }
}

// ---------------------------------------------------------------------------
// Bu GEMM wide-N: grid (16, 128). bx<8 -> Bt_re/bu_re, else Bt_im/bu_im.
// fp16 in, fp32 out (exact scan input).
// ---------------------------------------------------------------------------
__global__ void __launch_bounds__(256, 2)
bu_gemm_kernel() {
    extern __shared__ char smem[];

    const int tid = threadIdx.x;
    const int lane = tid & 31, qid = lane >> 2, qtr = lane & 3;
    const int wid = tid >> 5, wm = wid & 1, wn = wid >> 1;
    const int bxi = blockIdx.x;
    const int bn = (bxi & 7) * 128, bm = blockIdx.y * 128;

    const __half* Ag = g_x_h + (size_t)bm * 1024;
    const __half* Bg;
    float* Og;
    if (bxi < 8) { Bg = g_Bt_re + (size_t)bn * 1024; Og = g_bu_re; }
    else         { Bg = g_Bt_im + (size_t)bn * 1024; Og = g_bu_im; }

    FragCtx fc;
    init_frag_ctx(fc, lane, wm, wn);

    float acc[4][4][4];
    #pragma unroll
    for (int i = 0; i < 4; ++i)
        #pragma unroll
        for (int j = 0; j < 4; ++j)
            #pragma unroll
            for (int k = 0; k < 4; ++k) acc[i][j][k] = 0.f;

    #pragma unroll
    for (int p = 0; p < 2; ++p) {
        char* st = smem + p * STAGE_B;
        load_tile_h(st, Ag + p * 32);
        load_tile_h(st + HTILE_B, Bg + p * 32);
        CP_COMMIT();
    }

    const uint32_t sb = smem_u32(smem);
    #pragma unroll 1
    for (int c = 0; c < 32; ++c) {
        if (c + 2 < 32) { CP_WAIT(1); } else { CP_WAIT(0); }
        __syncthreads();
        if (c + 2 < 32) {
            char* st = smem + ((c + 2) % 3) * STAGE_B;
            load_tile_h(st, Ag + (c + 2) * 32);
            load_tile_h(st + HTILE_B, Bg + (c + 2) * 32);
            CP_COMMIT();
        }
        uint32_t A32 = sb + (c % 3) * STAGE_B;
        gemm_chunk(acc, fc, A32, A32 + HTILE_B);
        __syncthreads();
    }

    #pragma unroll
    for (int mt = 0; mt < 4; ++mt) {
        int r = bm + wm * 64 + mt * 16 + qid;
        #pragma unroll
        for (int nt = 0; nt < 4; ++nt) {
            int cc = bn + wn * 32 + nt * 8 + 2 * qtr;
            *reinterpret_cast<float2*>(Og + (size_t)r * 1024 + cc) =
                make_float2(acc[mt][nt][0], acc[mt][nt][1]);
            *reinterpret_cast<float2*>(Og + (size_t)(r + 8) * 1024 + cc) =
                make_float2(acc[mt][nt][2], acc[mt][nt][3]);
        }
    }
}

// ---------------------------------------------------------------------------
// Fused output GEMM: out = h_re@C_re^T + h_im@(-C_im)^T + x@Dt^T (all fp16 in)
// ---------------------------------------------------------------------------
__global__ void __launch_bounds__(256, 2)
out_gemm_kernel(float* __restrict__ out) {
    extern __shared__ char smem[];

    const int tid = threadIdx.x;
    const int lane = tid & 31, qid = lane >> 2, qtr = lane & 3;
    const int wid = tid >> 5, wm = wid & 1, wn = wid >> 1;
    const int bn = blockIdx.x * 128, bm = blockIdx.y * 128;

    const __half* Aseg[3];
    const __half* Bseg[3];
    Aseg[0] = g_h_re + (size_t)bm * 1024;
    Aseg[1] = g_h_im + (size_t)bm * 1024;
    Aseg[2] = g_x_h + (size_t)bm * 1024;
    Bseg[0] = g_Cre + (size_t)bn * 1024;
    Bseg[1] = g_nCim + (size_t)bn * 1024;
    Bseg[2] = g_Dt + (size_t)bn * 1024;

    FragCtx fc;
    init_frag_ctx(fc, lane, wm, wn);

    float acc[4][4][4];
    #pragma unroll
    for (int i = 0; i < 4; ++i)
        #pragma unroll
        for (int j = 0; j < 4; ++j)
            #pragma unroll
            for (int k = 0; k < 4; ++k) acc[i][j][k] = 0.f;

    #pragma unroll
    for (int p = 0; p < 2; ++p) {
        char* st = smem + p * STAGE_B;
        load_tile_h(st, Aseg[0] + p * 32);
        load_tile_h(st + HTILE_B, Bseg[0] + p * 32);
        CP_COMMIT();
    }

    const uint32_t sb = smem_u32(smem);
    #pragma unroll 1
    for (int c = 0; c < 96; ++c) {
        if (c + 2 < 96) { CP_WAIT(1); } else { CP_WAIT(0); }
        __syncthreads();
        if (c + 2 < 96) {
            int nc = c + 2, s = nc >> 5, kk = (nc & 31) * 32;
            char* st = smem + (nc % 3) * STAGE_B;
            load_tile_h(st, Aseg[s] + kk);
            load_tile_h(st + HTILE_B, Bseg[s] + kk);
            CP_COMMIT();
        }
        uint32_t A32 = sb + (c % 3) * STAGE_B;
        gemm_chunk(acc, fc, A32, A32 + HTILE_B);
        __syncthreads();
    }

    #pragma unroll
    for (int mt = 0; mt < 4; ++mt) {
        int r = bm + wm * 64 + mt * 16 + qid;
        #pragma unroll
        for (int nt = 0; nt < 4; ++nt) {
            int cc = bn + wn * 32 + nt * 8 + 2 * qtr;
            *reinterpret_cast<float2*>(out + (size_t)r * 1024 + cc) =
                make_float2(acc[mt][nt][0], acc[mt][nt][1]);
            *reinterpret_cast<float2*>(out + (size_t)(r + 8) * 1024 + cc) =
                make_float2(acc[mt][nt][2], acc[mt][nt][3]);
        }
    }
}

// ---------------------------------------------------------------------------
// Scan pass 1 (read-only): per-chunk end state. grid (2, NCHUNK), float2/thr.
// ---------------------------------------------------------------------------
__global__ void scan_sum_kernel() {
    int h2 = blockIdx.x * 512 + threadIdx.x * 2;
    int c = blockIdx.y;
    float2 lr2 = *reinterpret_cast<const float2*>(g_lam_re + h2);
    float2 li2 = *reinterpret_cast<const float2*>(g_lam_im + h2);
    float lr[2] = {lr2.x, lr2.y}, li[2] = {li2.x, li2.y};
    float sr[2] = {0, 0}, si[2] = {0, 0};
    const float* pre = g_bu_re + (size_t)c * CHUNK_L * H_DIM + h2;
    const float* pim = g_bu_im + (size_t)c * CHUNK_L * H_DIM + h2;
    #pragma unroll 4
    for (int j = 0; j < CHUNK_L; ++j) {
        float2 ur = *reinterpret_cast<const float2*>(pre + (size_t)j * H_DIM);
        float2 ui = *reinterpret_cast<const float2*>(pim + (size_t)j * H_DIM);
        const float urr[2] = {ur.x, ur.y};
        const float uii[2] = {ui.x, ui.y};
        #pragma unroll
        for (int q = 0; q < 2; ++q) {
            float nr = lr[q] * sr[q] - li[q] * si[q] + urr[q];
            float ni = lr[q] * si[q] + li[q] * sr[q] + uii[q];
            sr[q] = nr; si[q] = ni;
        }
    }
    *reinterpret_cast<float2*>(g_end_re + c * H_DIM + h2) = make_float2(sr[0], sr[1]);
    *reinterpret_cast<float2*>(g_end_im + c * H_DIM + h2) = make_float2(si[0], si[1]);
}

// ---------------------------------------------------------------------------
// Scan pass 2: carry chain across chunks (per h).
// ---------------------------------------------------------------------------
__global__ void scan_carry_kernel() {
    int h = blockIdx.x * blockDim.x + threadIdx.x;
    float Lr = g_lamL_re[h], Li = g_lamL_im[h];
    float cr = 0.f, ci = 0.f;
    for (int k = 0; k < NCHUNK; ++k) {
        g_carry_re[k * H_DIM + h] = cr;
        g_carry_im[k * H_DIM + h] = ci;
        float er = g_end_re[k * H_DIM + h];
        float ei = g_end_im[k * H_DIM + h];
        float nr = Lr * cr - Li * ci + er;
        float ni = Lr * ci + Li * cr + ei;
        cr = nr; ci = ni;
    }
}

// ---------------------------------------------------------------------------
// Scan pass 3: full scan seeded with carry; writes fp16 hidden states.
// grid (2, NCHUNK), float2 in / half2 out per thread.
// ---------------------------------------------------------------------------
__global__ void scan_full_kernel() {
    int h2 = blockIdx.x * 512 + threadIdx.x * 2;
    int c = blockIdx.y;
    float2 lr2 = *reinterpret_cast<const float2*>(g_lam_re + h2);
    float2 li2 = *reinterpret_cast<const float2*>(g_lam_im + h2);
    float2 cr2 = *reinterpret_cast<const float2*>(g_carry_re + c * H_DIM + h2);
    float2 ci2 = *reinterpret_cast<const float2*>(g_carry_im + c * H_DIM + h2);
    float lr[2] = {lr2.x, lr2.y}, li[2] = {li2.x, li2.y};
    float sr[2] = {cr2.x, cr2.y}, si[2] = {ci2.x, ci2.y};
    const float* pre = g_bu_re + (size_t)c * CHUNK_L * H_DIM + h2;
    const float* pim = g_bu_im + (size_t)c * CHUNK_L * H_DIM + h2;
    __half* hre = g_h_re + (size_t)c * CHUNK_L * H_DIM + h2;
    __half* him = g_h_im + (size_t)c * CHUNK_L * H_DIM + h2;
    #pragma unroll 4
    for (int j = 0; j < CHUNK_L; ++j) {
        float2 ur = *reinterpret_cast<const float2*>(pre + (size_t)j * H_DIM);
        float2 ui = *reinterpret_cast<const float2*>(pim + (size_t)j * H_DIM);
        const float urr[2] = {ur.x, ur.y};
        const float uii[2] = {ui.x, ui.y};
        #pragma unroll
        for (int q = 0; q < 2; ++q) {
            float nr = lr[q] * sr[q] - li[q] * si[q] + urr[q];
            float ni = lr[q] * si[q] + li[q] * sr[q] + uii[q];
            sr[q] = nr; si[q] = ni;
        }
        *reinterpret_cast<__half2*>(hre + (size_t)j * H_DIM) =
            __floats2half2_rn(sr[0], sr[1]);
        *reinterpret_cast<__half2*>(him + (size_t)j * H_DIM) =
            __floats2half2_rn(si[0], si[1]);
    }
}

// ---------------------------------------------------------------------------
// Launch
// ---------------------------------------------------------------------------
extern "C" void kernel_launch(void* const* d_in, const int* in_sizes, int n_in,
                              void* d_out, int out_size) {
    const float* x    = (const float*)d_in[0];
    const float* nu   = (const float*)d_in[1];
    const float* th   = (const float*)d_in[2];
    const float* ga   = (const float*)d_in[3];
    const float* B_re = (const float*)d_in[4];
    const float* B_im = (const float*)d_in[5];
    const float* C_re = (const float*)d_in[6];
    const float* C_im = (const float*)d_in[7];
    const float* Dm   = (const float*)d_in[8];
    float* out = (float*)d_out;

    __half *bt_re, *bt_im, *dt, *cre, *ncim, *xh;
    float* gam;
    cudaGetSymbolAddress((void**)&bt_re, g_Bt_re);
    cudaGetSymbolAddress((void**)&bt_im, g_Bt_im);
    cudaGetSymbolAddress((void**)&dt, g_Dt);
    cudaGetSymbolAddress((void**)&cre, g_Cre);
    cudaGetSymbolAddress((void**)&ncim, g_nCim);
    cudaGetSymbolAddress((void**)&xh, g_x_h);
    cudaGetSymbolAddress((void**)&gam, g_gam);

    cudaFuncSetAttribute(bu_gemm_kernel, cudaFuncAttributeMaxDynamicSharedMemorySize, GEMM_SMEM);
    cudaFuncSetAttribute(out_gemm_kernel, cudaFuncAttributeMaxDynamicSharedMemorySize, GEMM_SMEM);

    prep_kernel<<<H_DIM / 256, 256>>>(nu, th, ga);

    dim3 tgrid(32, 32), tblk(32, 8);
    transpose_kernel<<<tgrid, tblk>>>(B_re, bt_re, gam);
    transpose_kernel<<<tgrid, tblk>>>(B_im, bt_im, gam);
    transpose_kernel<<<tgrid, tblk>>>(Dm, dt, nullptr);
    convert_kernel<<<(OUT_DIM * H_DIM / 4) / 256, 256>>>(C_re, cre, 1.f);
    convert_kernel<<<(OUT_DIM * H_DIM / 4) / 256, 256>>>(C_im, ncim, -1.f);
    convert_kernel<<<((size_t)T_LEN * IN_DIM / 4) / 256, 256>>>(x, xh, 1.f);

    bu_gemm_kernel<<<dim3(16, T_LEN / 128), 256, GEMM_SMEM>>>();

    scan_sum_kernel<<<dim3(2, NCHUNK), 256>>>();
    scan_carry_kernel<<<H_DIM / 256, 256>>>();
    scan_full_kernel<<<dim3(2, NCHUNK), 256>>>();

    out_gemm_kernel<<<dim3(8, T_LEN / 128), 256, GEMM_SMEM>>>(out);
}